// round 4
// baseline (speedup 1.0000x reference)
#include <cuda_runtime.h>

// LSTMDecoder: B=1024, A=H=16, R=128, T=128.
// Layout: 16 threads per batch element (one per hidden index j).
// Lane j owns h_j, c_j, the 4 gate rows of W_hh (64 weights in registers),
// and window[j]. h broadcast + window ops via width-16 warp shuffles.
// 128 blocks x 128 threads = 16384 threads = 1024 batch * 16 -> single wave.

#define NB 1024
#define NT 128

__device__ __forceinline__ float sigf(float x) {
    // 1 / (1 + e^-x): EX2 + FADD + RCP (approx, ~2 ulp)
    return __fdividef(1.0f, 1.0f + __expf(-x));
}
__device__ __forceinline__ float tanhfast(float x) {
    // 2*sigmoid(2x) - 1
    float e = __expf(-2.0f * x);
    return fmaf(2.0f, __fdividef(1.0f, 1.0f + e), -1.0f);
}

__global__ __launch_bounds__(128, 1)
void lstm_decoder_kernel(
    const float* __restrict__ y,     // (B,16)
    const float* __restrict__ u,     // (B,128)
    const float* __restrict__ W_ih,  // (64,1)
    const float* __restrict__ W_hh,  // (64,16)
    const float* __restrict__ b_ih,  // (64)
    const float* __restrict__ b_hh,  // (64)
    const float* __restrict__ W_lin, // (1,16)
    const float* __restrict__ b_lin, // (1)
    const float* __restrict__ W_h0,  // (16,128)
    const float* __restrict__ b_h0,  // (16)
    const float* __restrict__ W_c0,  // (16,128)
    const float* __restrict__ b_c0,  // (16)
    float* __restrict__ out)         // (B,144)
{
    const int tid = blockIdx.x * blockDim.x + threadIdx.x;
    const int b   = tid >> 4;     // batch element
    const int j   = tid & 15;     // hidden index
    const unsigned FULL = 0xffffffffu;

    // ---- per-thread weights in registers ----
    float Wi[16], Wf[16], Wg[16], Wo[16];
#pragma unroll
    for (int k = 0; k < 16; k++) {
        Wi[k] = W_hh[(     j) * 16 + k];
        Wf[k] = W_hh[(16 + j) * 16 + k];
        Wg[k] = W_hh[(32 + j) * 16 + k];
        Wo[k] = W_hh[(48 + j) * 16 + k];
    }
    const float wii = W_ih[j],      wif = W_ih[16 + j];
    const float wig = W_ih[32 + j], wio = W_ih[48 + j];
    const float bi = b_ih[j]      + b_hh[j];
    const float bf = b_ih[16 + j] + b_hh[16 + j];
    const float bg = b_ih[32 + j] + b_hh[32 + j];
    const float bo = b_ih[48 + j] + b_hh[48 + j];
    const float wl = W_lin[j];
    const float bl = b_lin[0];

    // ---- h0 = u @ W_h0.T + b_h0 ; c0 = u @ W_c0.T + b_c0 ----
    float h = b_h0[j];
    float c = b_c0[j];
    {
        const float4* u4  = (const float4*)(u    + b * 128);
        const float4* wh4 = (const float4*)(W_h0 + j * 128);
        const float4* wc4 = (const float4*)(W_c0 + j * 128);
#pragma unroll 4
        for (int r = 0; r < 32; r++) {
            float4 uu = u4[r], wh = wh4[r], wc = wc4[r];
            h = fmaf(uu.x, wh.x, h); h = fmaf(uu.y, wh.y, h);
            h = fmaf(uu.z, wh.z, h); h = fmaf(uu.w, wh.w, h);
            c = fmaf(uu.x, wc.x, c); c = fmaf(uu.y, wc.y, c);
            c = fmaf(uu.z, wc.z, c); c = fmaf(uu.w, wc.w, c);
        }
    }

    // ---- window: lane j holds window[:, j] for this batch element ----
    float win = y[b * 16 + j];
    out[b * 144 + j] = win;                  // first 16 output cols = y
    float* outp = out + b * 144 + 16;

    for (int t = 0; t < NT; t++) {
        // 16 sequential LSTM cells over window columns 0..15
#pragma unroll 1
        for (int s = 0; s < 16; s++) {
            float x  = __shfl_sync(FULL, win, s, 16);
            float ai = fmaf(x, wii, bi);
            float af = fmaf(x, wif, bf);
            float ag = fmaf(x, wig, bg);
            float ao = fmaf(x, wio, bo);
#pragma unroll
            for (int k = 0; k < 16; k++) {
                float hk = __shfl_sync(FULL, h, k, 16);
                ai = fmaf(hk, Wi[k], ai);
                af = fmaf(hk, Wf[k], af);
                ag = fmaf(hk, Wg[k], ag);
                ao = fmaf(hk, Wo[k], ao);
            }
            float ig = sigf(ai);
            float fg = sigf(af);
            float gg = tanhfast(ag);
            float og = sigf(ao);
            c = fmaf(fg, c, ig * gg);
            h = og * tanhfast(c);
        }
        // pred = sum_j h_j * W_lin_j + b_lin  (butterfly over 16-lane segment)
        float p = h * wl;
#pragma unroll
        for (int off = 8; off; off >>= 1)
            p += __shfl_xor_sync(FULL, p, off, 16);
        p += bl;

        // window shift-left, append pred
        float nxt = __shfl_sync(FULL, win, j + 1, 16);   // j=15 wraps -> replaced
        win = (j == 15) ? p : nxt;

        if (j == 0) outp[t] = p;
    }
}

extern "C" void kernel_launch(void* const* d_in, const int* in_sizes, int n_in,
                              void* d_out, int out_size) {
    const float* y     = (const float*)d_in[0];
    const float* u     = (const float*)d_in[1];
    const float* W_ih  = (const float*)d_in[2];
    const float* W_hh  = (const float*)d_in[3];
    const float* b_ih  = (const float*)d_in[4];
    const float* b_hh  = (const float*)d_in[5];
    const float* W_lin = (const float*)d_in[6];
    const float* b_lin = (const float*)d_in[7];
    const float* W_h0  = (const float*)d_in[8];
    const float* b_h0  = (const float*)d_in[9];
    const float* W_c0  = (const float*)d_in[10];
    const float* b_c0  = (const float*)d_in[11];
    float* out = (float*)d_out;

    lstm_decoder_kernel<<<128, 128>>>(y, u, W_ih, W_hh, b_ih, b_hh,
                                      W_lin, b_lin, W_h0, b_h0, W_c0, b_c0, out);
}

// round 6
// speedup vs baseline: 1.5214x; 1.5214x over previous
#include <cuda_runtime.h>

// LSTMDecoder: B=1024, A=H=16, R=128, T=128.
// 16 threads per batch element; lane j owns h_j, c_j and 4 gate rows of W_hh.
// Serial-latency-bound problem: wallclock = 2048 * per-cell chain latency.
// R5 changes vs R4:
//   - tanh.approx.f32 MUFU for tanh and sigmoid (sig(x)=0.5+0.5*tanh(x/2))
//   - window replicated per-thread in xs[16] regs: no x shuffles, and the
//     pred butterfly reduction is off the critical path (feeds xs[15],
//     consumed 15 cells later)
//   - even/odd split accumulators per gate (chain depth 16 -> 8)

#define NT 128

__device__ __forceinline__ float tanhapx(float x) {
    float r;
    asm("tanh.approx.f32 %0, %1;" : "=f"(r) : "f"(x));
    return r;
}
__device__ __forceinline__ float sigapx(float x) {
    return fmaf(0.5f, tanhapx(0.5f * x), 0.5f);
}

__global__ __launch_bounds__(128, 1)
void lstm_decoder_kernel(
    const float* __restrict__ y,     // (B,16)
    const float* __restrict__ u,     // (B,128)
    const float* __restrict__ W_ih,  // (64,1)
    const float* __restrict__ W_hh,  // (64,16)
    const float* __restrict__ b_ih,  // (64)
    const float* __restrict__ b_hh,  // (64)
    const float* __restrict__ W_lin, // (1,16)
    const float* __restrict__ b_lin, // (1)
    const float* __restrict__ W_h0,  // (16,128)
    const float* __restrict__ b_h0,  // (16)
    const float* __restrict__ W_c0,  // (16,128)
    const float* __restrict__ b_c0,  // (16)
    float* __restrict__ out)         // (B,144)
{
    const int tid = blockIdx.x * blockDim.x + threadIdx.x;
    const int b   = tid >> 4;     // batch element
    const int j   = tid & 15;     // hidden index
    const unsigned FULL = 0xffffffffu;

    // ---- per-thread weights in registers ----
    float Wi[16], Wf[16], Wg[16], Wo[16];
#pragma unroll
    for (int k = 0; k < 16; k++) {
        Wi[k] = W_hh[(     j) * 16 + k];
        Wf[k] = W_hh[(16 + j) * 16 + k];
        Wg[k] = W_hh[(32 + j) * 16 + k];
        Wo[k] = W_hh[(48 + j) * 16 + k];
    }
    const float wii = W_ih[j],      wif = W_ih[16 + j];
    const float wig = W_ih[32 + j], wio = W_ih[48 + j];
    const float bi = b_ih[j]      + b_hh[j];
    const float bf = b_ih[16 + j] + b_hh[16 + j];
    const float bg = b_ih[32 + j] + b_hh[32 + j];
    const float bo = b_ih[48 + j] + b_hh[48 + j];
    const float wl = W_lin[j];
    const float bl = b_lin[0];

    // ---- h0 = u @ W_h0.T + b_h0 ; c0 = u @ W_c0.T + b_c0 ----
    float h = b_h0[j];
    float c = b_c0[j];
    {
        const float4* u4  = (const float4*)(u    + b * 128);
        const float4* wh4 = (const float4*)(W_h0 + j * 128);
        const float4* wc4 = (const float4*)(W_c0 + j * 128);
#pragma unroll 4
        for (int r = 0; r < 32; r++) {
            float4 uu = u4[r], wh = wh4[r], wc = wc4[r];
            h = fmaf(uu.x, wh.x, h); h = fmaf(uu.y, wh.y, h);
            h = fmaf(uu.z, wh.z, h); h = fmaf(uu.w, wh.w, h);
            c = fmaf(uu.x, wc.x, c); c = fmaf(uu.y, wc.y, c);
            c = fmaf(uu.z, wc.z, c); c = fmaf(uu.w, wc.w, c);
        }
    }

    // ---- window replicated per-thread: xs[s] = window[:, s] ----
    float xs[16];
    {
        const float4* y4 = (const float4*)(y + b * 16);
        float4 y0 = y4[0], y1 = y4[1], y2 = y4[2], y3 = y4[3];
        xs[0]=y0.x; xs[1]=y0.y; xs[2]=y0.z; xs[3]=y0.w;
        xs[4]=y1.x; xs[5]=y1.y; xs[6]=y1.z; xs[7]=y1.w;
        xs[8]=y2.x; xs[9]=y2.y; xs[10]=y2.z; xs[11]=y2.w;
        xs[12]=y3.x; xs[13]=y3.y; xs[14]=y3.z; xs[15]=y3.w;
    }
    out[b * 144 + j] = y[b * 16 + j];        // first 16 output cols = y
    float* outp = out + b * 144 + 16;

    for (int t = 0; t < NT; t++) {
        // 16 sequential LSTM cells over window (fully unrolled; xs static)
#pragma unroll
        for (int s = 0; s < 16; s++) {
            float x = xs[s];
            float ai0 = fmaf(x, wii, bi), ai1 = 0.0f;
            float af0 = fmaf(x, wif, bf), af1 = 0.0f;
            float ag0 = fmaf(x, wig, bg), ag1 = 0.0f;
            float ao0 = fmaf(x, wio, bo), ao1 = 0.0f;
#pragma unroll
            for (int k = 0; k < 16; k += 2) {
                float h0 = __shfl_sync(FULL, h, k,     16);
                float h1 = __shfl_sync(FULL, h, k + 1, 16);
                ai0 = fmaf(h0, Wi[k], ai0); ai1 = fmaf(h1, Wi[k+1], ai1);
                af0 = fmaf(h0, Wf[k], af0); af1 = fmaf(h1, Wf[k+1], af1);
                ag0 = fmaf(h0, Wg[k], ag0); ag1 = fmaf(h1, Wg[k+1], ag1);
                ao0 = fmaf(h0, Wo[k], ao0); ao1 = fmaf(h1, Wo[k+1], ao1);
            }
            float ig = sigapx(ai0 + ai1);
            float fg = sigapx(af0 + af1);
            float gg = tanhapx(ag0 + ag1);
            float og = sigapx(ao0 + ao1);
            c = fmaf(fg, c, ig * gg);
            h = og * tanhapx(c);
        }
        // pred = sum_j h_j * W_lin_j + b_lin (off critical path: feeds xs[15],
        // which is consumed only at cell s=15 of the NEXT step)
        float p = h * wl;
#pragma unroll
        for (int off = 8; off; off >>= 1)
            p += __shfl_xor_sync(FULL, p, off, 16);
        p += bl;

        if (j == 0) outp[t] = p;

#pragma unroll
        for (int s = 0; s < 15; s++) xs[s] = xs[s + 1];
        xs[15] = p;
    }
}

extern "C" void kernel_launch(void* const* d_in, const int* in_sizes, int n_in,
                              void* d_out, int out_size) {
    const float* y     = (const float*)d_in[0];
    const float* u     = (const float*)d_in[1];
    const float* W_ih  = (const float*)d_in[2];
    const float* W_hh  = (const float*)d_in[3];
    const float* b_ih  = (const float*)d_in[4];
    const float* b_hh  = (const float*)d_in[5];
    const float* W_lin = (const float*)d_in[6];
    const float* b_lin = (const float*)d_in[7];
    const float* W_h0  = (const float*)d_in[8];
    const float* b_h0  = (const float*)d_in[9];
    const float* W_c0  = (const float*)d_in[10];
    const float* b_c0  = (const float*)d_in[11];
    float* out = (float*)d_out;

    lstm_decoder_kernel<<<128, 128>>>(y, u, W_ih, W_hh, b_ih, b_hh,
                                      W_lin, b_lin, W_h0, b_h0, W_c0, b_c0, out);
}